// round 9
// baseline (speedup 1.0000x reference)
#include <cuda_runtime.h>
#include <cstdint>

#define DTC   0.001f
#define HID   512
#define NOUT  128
#define SEQL  2048
#define NB    64
#define MROWS (SEQL * NB)     // 131072 output rows, m = s*64 + b
#define NCH   (NB * NOUT)     // 8192 recurrence chains
#define SEG_P 32
#define SEG_L 64

#define XMAX  6.0f
#define WMAX  0.046875f
#define XSCL  (32512.0f / XMAX)
#define WSCL  (32512.0f / WMAX)

// ---------------- scratch (no allocation allowed) ----------------
__device__ __align__(16) float g_segE_v[SEG_P * NCH];
__device__ __align__(16) float g_segE_i[SEG_P * NCH];
__device__ __align__(16) float g_init_v[SEG_P * NCH];
__device__ __align__(16) float g_init_i[SEG_P * NCH];
__device__ __align__(16) int8_t g_Wq1[NOUT * HID];
__device__ __align__(16) int8_t g_Wq2[NOUT * HID];

// ---------------- helpers ----------------
__device__ __forceinline__ uint32_t smem_u32(const void* p) {
    uint32_t a;
    asm("{ .reg .u64 t; cvta.to.shared.u64 t, %1; cvt.u32.u64 %0, t; }" : "=r"(a) : "l"(p));
    return a;
}
__device__ __forceinline__ void ldsm_x4(uint32_t* r, uint32_t addr) {
    asm volatile("ldmatrix.sync.aligned.m8n8.x4.shared.b16 {%0,%1,%2,%3}, [%4];"
                 : "=r"(r[0]), "=r"(r[1]), "=r"(r[2]), "=r"(r[3]) : "r"(addr));
}
__device__ __forceinline__ void mma_s8(int* c, const uint32_t* a,
                                       uint32_t b0, uint32_t b1) {
    asm volatile(
        "mma.sync.aligned.m16n8k32.row.col.s32.s8.s8.s32 "
        "{%0,%1,%2,%3}, {%4,%5,%6,%7}, {%8,%9}, {%0,%1,%2,%3};"
        : "+r"(c[0]), "+r"(c[1]), "+r"(c[2]), "+r"(c[3])
        : "r"(a[0]), "r"(a[1]), "r"(a[2]), "r"(a[3]), "r"(b0), "r"(b1));
}
__device__ __forceinline__ void cp16(uint32_t smaddr, const void* g) {
    asm volatile("cp.async.cg.shared.global [%0], [%1], 16;"
                 :: "r"(smaddr), "l"(g) : "memory");
}
#define CP_COMMIT() asm volatile("cp.async.commit_group;" ::: "memory")
#define CP_WAIT(n)  asm volatile("cp.async.wait_group %0;" :: "n"(n) : "memory")
#define BAR_SYNC(id, cnt)   asm volatile("bar.sync %0, %1;"   :: "r"(id), "r"(cnt) : "memory")
#define BAR_ARRIVE(id, cnt) asm volatile("bar.arrive %0, %1;" :: "r"(id), "r"(cnt) : "memory")

// exact two-level int8 quantization: i = rint(x*s) = 256*q1 + q2
__device__ __forceinline__ void quant4i(float4 f, float s,
                                        uint32_t& k1, uint32_t& k2) {
    const int j0 = __float2int_rn(fminf(fmaxf(f.x * s, -32512.f), 32512.f)) + 128;
    const int j1 = __float2int_rn(fminf(fmaxf(f.y * s, -32512.f), 32512.f)) + 128;
    const int j2 = __float2int_rn(fminf(fmaxf(f.z * s, -32512.f), 32512.f)) + 128;
    const int j3 = __float2int_rn(fminf(fmaxf(f.w * s, -32512.f), 32512.f)) + 128;
    uint32_t h01 = __byte_perm((uint32_t)(j0 >> 8), (uint32_t)(j1 >> 8), 0x0040);
    uint32_t h23 = __byte_perm((uint32_t)(j2 >> 8), (uint32_t)(j3 >> 8), 0x0040);
    k1 = __byte_perm(h01, h23, 0x5410);
    uint32_t l01 = __byte_perm((uint32_t)j0, (uint32_t)j1, 0x0040);
    uint32_t l23 = __byte_perm((uint32_t)j2, (uint32_t)j3, 0x0040);
    k2 = __byte_perm(l01, l23, 0x5410) ^ 0x80808080u;
}

// ---------------------------------------------------------------------------
__global__ __launch_bounds__(256)
void w_prequant(const float* __restrict__ W) {
    const int i = blockIdx.x * 256 + threadIdx.x;
    const int j = __float2int_rn(fminf(fmaxf(W[i] * WSCL, -32512.f), 32512.f)) + 128;
    g_Wq1[i] = (int8_t)(j >> 8);
    g_Wq2[i] = (int8_t)((j & 255) - 128);
}

// ---------------------------------------------------------------------------
// Warp-specialized int8 GEMM. 320 threads: warps 0-7 consume (64x32 warp tile,
// ldsm + 3-product IMMA only), warps 8-9 produce A (LDG fp32 -> quant -> STS,
// 4-stage ring, named-barrier handshake). B (whole K) persistent in SMEM.
// ---------------------------------------------------------------------------
#define ROWB    80
#define ASTGB   (2 * 128 * ROWB)     // Aq1+Aq2 per stage = 20480
#define SMB_B   (4 * ASTGB)          // 81920: B base
#define BROWB   528                  // 512B K + 16B pad (ldsm conflict-free)
#define BMATB   (128 * BROWB)        // 67584 per matrix
#define SMEMB   (SMB_B + 2 * BMATB)  // 217088

extern __shared__ char dynsmem[];

__global__ __launch_bounds__(320, 1)
void snn_gemm_i8(const float* __restrict__ x, float* __restrict__ z) {
    const int tid  = threadIdx.x;
    const int wid  = tid >> 5;
    const int lane = tid & 31;
    const int m0   = blockIdx.x * 128;

    const uint32_t sm = smem_u32(dynsmem);

    // ---- prologue: everyone loads persistent B (2 x 128 rows x 512B) ----
    for (int idx = tid; idx < 8192; idx += 320) {
        const int mat = idx >> 12;
        const int rem = idx & 4095;
        const int row = rem >> 5;
        const int q   = rem & 31;
        const int8_t* src = (mat ? g_Wq2 : g_Wq1) + row * 512 + q * 16;
        cp16(sm + SMB_B + (uint32_t)mat * BMATB + (uint32_t)row * BROWB + q * 16, src);
    }
    CP_COMMIT();
    CP_WAIT(0);
    __syncthreads();

    if (wid < 8) {
        // ================= CONSUMERS =================
        const int wm = wid & 1;      // 2 M groups of 64
        const int wn = wid >> 1;     // 4 N groups of 32

        uint32_t aAddr[4];
#pragma unroll
        for (int i = 0; i < 4; i++) {
            const int arow = wm * 64 + i * 16 + (lane & 7) + ((lane >> 3) & 1) * 8;
            aAddr[i] = sm + (uint32_t)arow * ROWB + ((lane >> 4) & 1) * 16;
        }
        uint32_t bAddr[2];
#pragma unroll
        for (int g = 0; g < 2; g++) {
            const int bcol = wn * 32 + g * 16 + (lane & 7) + ((lane >> 4) & 1) * 8;
            bAddr[g] = sm + SMB_B + (uint32_t)bcol * BROWB + ((lane >> 3) & 1) * 16;
        }

        int accH[4][4][4], accX[4][4][4];
#pragma unroll
        for (int i = 0; i < 4; i++)
#pragma unroll
            for (int j = 0; j < 4; j++)
#pragma unroll
                for (int q = 0; q < 4; q++) { accH[i][j][q] = 0; accX[i][j][q] = 0; }

#pragma unroll
        for (int c = 0; c < 8; c++) {
            const int s = c & 3;
            BAR_SYNC(1 + s, 320);                       // wait stage full
            const uint32_t ab = (uint32_t)s * ASTGB;
#pragma unroll
            for (int ks = 0; ks < 2; ks++) {
                const uint32_t ao = ab + (uint32_t)ks * 32;
                const uint32_t bo = (uint32_t)(c * 64 + ks * 32);
                uint32_t a1[4][4], a2[4][4];
#pragma unroll
                for (int i = 0; i < 4; i++) {
                    ldsm_x4(a1[i], aAddr[i] + ao);
                    ldsm_x4(a2[i], aAddr[i] + ao + 128 * ROWB);
                }
                uint32_t b1[8], b2[8];
                ldsm_x4(b1 + 0, bAddr[0] + bo);
                ldsm_x4(b1 + 4, bAddr[1] + bo);
                ldsm_x4(b2 + 0, bAddr[0] + bo + BMATB);
                ldsm_x4(b2 + 4, bAddr[1] + bo + BMATB);
#pragma unroll
                for (int i = 0; i < 4; i++)
#pragma unroll
                    for (int j = 0; j < 4; j++) {
                        mma_s8(accH[i][j], a1[i], b1[2 * j], b1[2 * j + 1]);
                        mma_s8(accX[i][j], a1[i], b2[2 * j], b2[2 * j + 1]);
                        mma_s8(accX[i][j], a2[i], b1[2 * j], b1[2 * j + 1]);
                    }
            }
            BAR_ARRIVE(5 + s, 320);                     // stage empty
        }

        // ---- epilogue ----
        const double sxw = ((double)XMAX / 32512.0) * ((double)WMAX / 32512.0);
        const float SC1 = (float)(sxw * 65536.0);
        const float SC2 = (float)(sxw * 256.0);
        const int r0 = lane >> 2;
        const int c0 = (lane & 3) * 2;
#pragma unroll
        for (int i = 0; i < 4; i++) {
            const int mrow = m0 + wm * 64 + i * 16 + r0;
#pragma unroll
            for (int j = 0; j < 4; j++) {
                const int col = wn * 32 + j * 8 + c0;
                float z0 = SC1 * (float)accH[i][j][0] + SC2 * (float)accX[i][j][0];
                float z1 = SC1 * (float)accH[i][j][1] + SC2 * (float)accX[i][j][1];
                float z2 = SC1 * (float)accH[i][j][2] + SC2 * (float)accX[i][j][2];
                float z3 = SC1 * (float)accH[i][j][3] + SC2 * (float)accX[i][j][3];
                *(float2*)&z[(size_t)mrow * NOUT + col] = make_float2(z0, z1);
                *(float2*)&z[(size_t)(mrow + 8) * NOUT + col] = make_float2(z2, z3);
            }
        }
    } else {
        // ================= PRODUCERS (warps 8-9) =================
        const int ptid = tid - 256;           // 0..63
        const int rowA = ptid;                // first row
        const int rowB = ptid + 64;           // second row
        const int mA = m0 + rowA, mB = m0 + rowB;
        const float* srcA = x + ((size_t)(mA & 63) * SEQL + (size_t)(mA >> 6)) * HID;
        const float* srcB = x + ((size_t)(mB & 63) * SEQL + (size_t)(mB >> 6)) * HID;

        float4 fA[16], fB[16];
#pragma unroll
        for (int i = 0; i < 16; i++) fA[i] = *(const float4*)(srcA + i * 4);

        for (int c = 0; c < 8; c++) {
            const int s = c & 3;
            if (c >= 4) BAR_SYNC(5 + s, 320);           // wait stage empty
            // row B of this chunk: issue loads now, consume after row A quant
#pragma unroll
            for (int i = 0; i < 16; i++) fB[i] = *(const float4*)(srcB + c * 64 + i * 4);

            char* base = dynsmem + s * ASTGB;
            {   // quant + store row A
                uint32_t k1[16], k2[16];
#pragma unroll
                for (int i = 0; i < 16; i++) quant4i(fA[i], XSCL, k1[i], k2[i]);
                char* p1 = base + rowA * ROWB;
                char* p2 = p1 + 128 * ROWB;
#pragma unroll
                for (int q = 0; q < 4; q++) {
                    *(uint4*)(p1 + q * 16) = make_uint4(k1[4*q], k1[4*q+1], k1[4*q+2], k1[4*q+3]);
                    *(uint4*)(p2 + q * 16) = make_uint4(k2[4*q], k2[4*q+1], k2[4*q+2], k2[4*q+3]);
                }
            }
            // prefetch row A of next chunk while row B data arrives
            if (c < 7) {
#pragma unroll
                for (int i = 0; i < 16; i++) fA[i] = *(const float4*)(srcA + (c + 1) * 64 + i * 4);
            }
            {   // quant + store row B
                uint32_t k1[16], k2[16];
#pragma unroll
                for (int i = 0; i < 16; i++) quant4i(fB[i], XSCL, k1[i], k2[i]);
                char* p1 = base + rowB * ROWB;
                char* p2 = p1 + 128 * ROWB;
#pragma unroll
                for (int q = 0; q < 4; q++) {
                    *(uint4*)(p1 + q * 16) = make_uint4(k1[4*q], k1[4*q+1], k1[4*q+2], k1[4*q+3]);
                    *(uint4*)(p2 + q * 16) = make_uint4(k2[4*q], k2[4*q+1], k2[4*q+2], k2[4*q+3]);
                }
            }
            BAR_ARRIVE(1 + s, 320);                     // stage full
        }
    }
}

// ---------------------------------------------------------------------------
// Scan stage A: zero-state segment responses, 4 chains per thread (float4).
// ---------------------------------------------------------------------------
__global__ __launch_bounds__(256)
void scan_segA(const float* __restrict__ zv,
               const float* __restrict__ tau_syn, const float* __restrict__ tau_mem) {
    const int t = blockIdx.x * 256 + threadIdx.x;
    const int ch4 = (t & 2047) * 4;
    const int p = t >> 11;
    const float tm = fminf(fmaxf(tau_mem[0], 0.f), 1.f);
    const float ts = fminf(fmaxf(tau_syn[0], 0.f), 1.f);
    const float A = DTC * tm, B = DTC * ts;

    const float* zp = zv + (size_t)(p * SEG_L) * NCH + ch4;
    float v[4] = {0, 0, 0, 0}, cu[4] = {0, 0, 0, 0};
    float4 buf[8];
#pragma unroll
    for (int g = 0; g < SEG_L; g += 8) {
#pragma unroll
        for (int j = 0; j < 8; j++) buf[j] = *(const float4*)(zp + (g + j) * NCH);
#pragma unroll
        for (int j = 0; j < 8; j++) {
            const float* zb = (const float*)&buf[j];
#pragma unroll
            for (int q = 0; q < 4; q++) {
                v[q]  = fmaf(A, cu[q] - v[q], v[q]);
                cu[q] = fmaf(-B, cu[q], cu[q]) + zb[q];
            }
        }
    }
    *(float4*)&g_segE_v[p * NCH + ch4] = make_float4(v[0], v[1], v[2], v[3]);
    *(float4*)&g_segE_i[p * NCH + ch4] = make_float4(cu[0], cu[1], cu[2], cu[3]);
}

// ---------------------------------------------------------------------------
// Scan stage B: per chain, scan SEG_P summaries (all loads prefetched).
// ---------------------------------------------------------------------------
__global__ __launch_bounds__(256)
void scan_segB(const float* __restrict__ tau_syn, const float* __restrict__ tau_mem) {
    const int chain = blockIdx.x * 256 + threadIdx.x;
    const float tm = fminf(fmaxf(tau_mem[0], 0.f), 1.f);
    const float ts = fminf(fmaxf(tau_syn[0], 0.f), 1.f);
    const float A = DTC * tm, B = DTC * ts;
    const float a = 1.f - A, b = 1.f - B;

    float ev[SEG_P], ei[SEG_P];
#pragma unroll
    for (int p = 0; p < SEG_P; p++) {
        ev[p] = g_segE_v[p * NCH + chain];
        ei[p] = g_segE_i[p * NCH + chain];
    }

    float pa = 1.f, pc = 0.f, pb = 1.f;   // M^SEG_L = [[pa,pc],[0,pb]]
#pragma unroll
    for (int k = 0; k < SEG_L; k++) {
        pc = a * pc + A * pb;
        pa = a * pa;
        pb = b * pb;
    }

    float v = 0.f, cur = 0.f;
#pragma unroll
    for (int p = 0; p < SEG_P; p++) {
        g_init_v[p * NCH + chain] = v;
        g_init_i[p * NCH + chain] = cur;
        const float nv = pa * v + pc * cur + ev[p];
        const float ni = pb * cur + ei[p];
        v = nv; cur = ni;
    }
}

// ---------------------------------------------------------------------------
// Scan stage C: exact per-segment recompute + in-place voltage write, x4.
// ---------------------------------------------------------------------------
__global__ __launch_bounds__(256)
void scan_segC(float* __restrict__ zv, float* __restrict__ vf, float* __restrict__ iff,
               const float* __restrict__ tau_syn, const float* __restrict__ tau_mem,
               int write_finals) {
    const int t = blockIdx.x * 256 + threadIdx.x;
    const int ch4 = (t & 2047) * 4;
    const int p = t >> 11;
    const float tm = fminf(fmaxf(tau_mem[0], 0.f), 1.f);
    const float ts = fminf(fmaxf(tau_syn[0], 0.f), 1.f);
    const float A = DTC * tm, B = DTC * ts;

    float4 v4 = *(const float4*)&g_init_v[p * NCH + ch4];
    float4 i4 = *(const float4*)&g_init_i[p * NCH + ch4];
    float v[4] = {v4.x, v4.y, v4.z, v4.w};
    float cu[4] = {i4.x, i4.y, i4.z, i4.w};

    float* zp = zv + (size_t)(p * SEG_L) * NCH + ch4;
    float4 buf[8];
#pragma unroll
    for (int g = 0; g < SEG_L; g += 8) {
#pragma unroll
        for (int j = 0; j < 8; j++) buf[j] = *(const float4*)(zp + (g + j) * NCH);
#pragma unroll
        for (int j = 0; j < 8; j++) {
            const float* zb = (const float*)&buf[j];
            float4 vo;
#pragma unroll
            for (int q = 0; q < 4; q++) {
                v[q] = fmaf(A, cu[q] - v[q], v[q]);
                ((float*)&vo)[q] = v[q];
                cu[q] = fmaf(-B, cu[q], cu[q]) + zb[q];
            }
            *(float4*)(zp + (g + j) * NCH) = vo;
        }
    }
    if (write_finals && p == SEG_P - 1) {
        *(float4*)&vf[ch4]  = make_float4(v[0], v[1], v[2], v[3]);
        *(float4*)&iff[ch4] = make_float4(cu[0], cu[1], cu[2], cu[3]);
    }
}

// ---------------------------------------------------------------------------
extern "C" void kernel_launch(void* const* d_in, const int* in_sizes, int n_in,
                              void* d_out, int out_size) {
    const float* x = nullptr;
    const float* W = nullptr;
    const float* t_syn = nullptr;
    const float* t_mem = nullptr;
    for (int i = 0; i < n_in; i++) {
        if (in_sizes[i] == MROWS * HID)     x = (const float*)d_in[i];
        else if (in_sizes[i] == NOUT * HID) W = (const float*)d_in[i];
        else if (in_sizes[i] == 1) {
            if (!t_syn) t_syn = (const float*)d_in[i];
            else        t_mem = (const float*)d_in[i];
        }
    }

    float* out = (float*)d_out;
    const int vol = SEQL * NCH;
    const int write_finals = (out_size >= vol + 2 * NCH) ? 1 : 0;

    static int smem_set = 0;
    if (!smem_set) {
        cudaFuncSetAttribute(snn_gemm_i8,
                             cudaFuncAttributeMaxDynamicSharedMemorySize, SMEMB);
        smem_set = 1;
    }

    w_prequant<<<(NOUT * HID) / 256, 256>>>(W);
    snn_gemm_i8<<<MROWS / 128, 320, SMEMB>>>(x, out);
    scan_segA<<<(SEG_P * NCH / 4) / 256, 256>>>(out, t_syn, t_mem);
    scan_segB<<<NCH / 256, 256>>>(t_syn, t_mem);
    scan_segC<<<(SEG_P * NCH / 4) / 256, 256>>>(out, out + vol, out + vol + NCH,
                                                t_syn, t_mem, write_finals);
}

// round 10
// speedup vs baseline: 1.6287x; 1.6287x over previous
#include <cuda_runtime.h>
#include <cuda_fp16.h>
#include <cstdint>

#define DTC   0.001f
#define HID   512
#define NOUT  128
#define SEQL  2048
#define NB    64
#define MROWS (SEQL * NB)     // 131072 output rows, m = s*64 + b
#define NCH   (NB * NOUT)     // 8192 recurrence chains
#define SEG_P 32
#define SEG_L 64

// ---------------- scratch (no allocation allowed) ----------------
__device__ __align__(16) float g_segE_v[SEG_P * NCH];
__device__ __align__(16) float g_segE_i[SEG_P * NCH];
__device__ __align__(16) float g_init_v[SEG_P * NCH];
__device__ __align__(16) float g_init_i[SEG_P * NCH];
__device__ __align__(16) __half g_Wh[NOUT * HID];

// ---------------- helpers ----------------
__device__ __forceinline__ uint32_t smem_u32(const void* p) {
    uint32_t a;
    asm("{ .reg .u64 t; cvta.to.shared.u64 t, %1; cvt.u32.u64 %0, t; }" : "=r"(a) : "l"(p));
    return a;
}
__device__ __forceinline__ void ldsm_x4(uint32_t* r, uint32_t addr) {
    asm volatile("ldmatrix.sync.aligned.m8n8.x4.shared.b16 {%0,%1,%2,%3}, [%4];"
                 : "=r"(r[0]), "=r"(r[1]), "=r"(r[2]), "=r"(r[3]) : "r"(addr));
}
__device__ __forceinline__ void mma_f16(float* c, const uint32_t* a,
                                        uint32_t b0, uint32_t b1) {
    asm volatile(
        "mma.sync.aligned.m16n8k16.row.col.f32.f16.f16.f32 "
        "{%0,%1,%2,%3}, {%4,%5,%6,%7}, {%8,%9}, {%0,%1,%2,%3};"
        : "+f"(c[0]), "+f"(c[1]), "+f"(c[2]), "+f"(c[3])
        : "r"(a[0]), "r"(a[1]), "r"(a[2]), "r"(a[3]), "r"(b0), "r"(b1));
}
__device__ __forceinline__ void cp16(uint32_t smaddr, const void* g) {
    asm volatile("cp.async.cg.shared.global [%0], [%1], 16;"
                 :: "r"(smaddr), "l"(g) : "memory");
}
#define CP_COMMIT() asm volatile("cp.async.commit_group;" ::: "memory")
#define CP_WAIT0()  asm volatile("cp.async.wait_group 0;" ::: "memory")

__device__ __forceinline__ uint32_t h2u(__half2 v) {
    return *reinterpret_cast<uint32_t*>(&v);
}
// split float4 into fp16-hi (k1,k2 packed half2) and fp16-residual (l1,l2)
__device__ __forceinline__ void split4h(float4 f, uint2& hi, uint2& lo) {
    __half2 a = __floats2half2_rn(f.x, f.y);
    __half2 b = __floats2half2_rn(f.z, f.w);
    float rx = f.x - __half2float(__low2half(a));
    float ry = f.y - __half2float(__high2half(a));
    float rz = f.z - __half2float(__low2half(b));
    float rw = f.w - __half2float(__high2half(b));
    hi.x = h2u(a); hi.y = h2u(b);
    lo.x = h2u(__floats2half2_rn(rx, ry));
    lo.y = h2u(__floats2half2_rn(rz, rw));
}

// ---------------------------------------------------------------------------
// W pre-conversion fp32 -> fp16, once per launch.
// ---------------------------------------------------------------------------
__global__ __launch_bounds__(256)
void w_preconv(const float* __restrict__ W) {
    const int i = blockIdx.x * 256 + threadIdx.x;
    g_Wh[i] = __float2half_rn(W[i]);
}

// ---------------------------------------------------------------------------
// GEMM: z = x*W via 2-product fp16 mma (x = h1+h2 exact fp16 split, W = fp16).
// CTA 128x128, BK=64 (8 chunks), double-buffered SMEM, 256 threads / 8 warps,
// warp tile 64x32. A: LDG fp32 + split + STS. B: cp.async fp16 (1 matrix!).
// Both products accumulate into ONE fp32 acc (same scale). Rows 128B pad 144B.
// ---------------------------------------------------------------------------
#define ROWB   144
#define MATB   (128 * ROWB)          // 18432 bytes per matrix
#define BUFB   (3 * MATB)            // Ah1, Ah2, B = 55296
#define SMEMB  (2 * BUFB)            // 110592 bytes

extern __shared__ char dynsmem[];

__global__ __launch_bounds__(256, 1)
void snn_gemm_f16(const float* __restrict__ x, float* __restrict__ z) {
    const int tid  = threadIdx.x;
    const int wid  = tid >> 5;
    const int lane = tid & 31;
    const int m0   = blockIdx.x * 128;
    const int wm   = wid & 1;        // 2 M groups of 64
    const int wn   = wid >> 1;       // 4 N groups of 32

    const uint32_t sm = smem_u32(dynsmem);

    // ---- A global load mapping: row = tid>>1, 32-float half = (tid&1)*32 ----
    const int rA = tid >> 1;
    const int hA = (tid & 1) * 32;
    const int mA = m0 + rA;
    const float* pA = x + ((size_t)(mA & 63) * SEQL + (size_t)(mA >> 6)) * HID + hA;
    const uint32_t st0 = (uint32_t)rA * ROWB + (uint32_t)hA * 2;   // fp16 bytes

    // ---- B cp.async mapping: row = tid>>1, 64B half = (tid&1)*64 ----
    const __half* pB = g_Wh + (size_t)rA * HID + hA;
    const uint32_t bDst = (uint32_t)(2 * MATB) + (uint32_t)rA * ROWB + (uint32_t)hA * 2;

    // ---- ldsm source addresses (R3-proven b16 mappings, ROWB=144) ----
    uint32_t aAddr[4];
#pragma unroll
    for (int i = 0; i < 4; i++) {
        const int arow = wm * 64 + i * 16 + (lane & 15);
        aAddr[i] = sm + (uint32_t)arow * ROWB + ((lane >> 4) & 1) * 16;
    }
    uint32_t bAddr[2];
#pragma unroll
    for (int g = 0; g < 2; g++) {
        const int bcol = wn * 32 + g * 16 + ((lane >> 4) & 1) * 8 + (lane & 7);
        bAddr[g] = sm + (uint32_t)(2 * MATB) + (uint32_t)bcol * ROWB +
                   ((lane >> 3) & 1) * 16;
    }

    float acc[4][4][4];
#pragma unroll
    for (int i = 0; i < 4; i++)
#pragma unroll
        for (int j = 0; j < 4; j++)
#pragma unroll
            for (int q = 0; q < 4; q++) acc[i][j][q] = 0.f;

    float4 rgA[8];
    auto loadA = [&](int c) {
#pragma unroll
        for (int q = 0; q < 8; q++) rgA[q] = *(const float4*)(pA + c * 64 + q * 4);
    };
    auto storeA = [&](char* base) {
#pragma unroll
        for (int q = 0; q < 8; q++) {
            uint2 hi, lo;
            split4h(rgA[q], hi, lo);
            const uint32_t o = st0 + (uint32_t)q * 8;
            *(uint2*)(base + o) = hi;
            *(uint2*)(base + MATB + o) = lo;
        }
    };
    auto cpB = [&](uint32_t bufb, int c) {
        const uint32_t d = sm + bufb + bDst;
        const __half* s = pB + c * 64;
#pragma unroll
        for (int k = 0; k < 4; k++) cp16(d + k * 16, s + k * 8);
    };

    // ---- prologue ----
    loadA(0);
    storeA(dynsmem);
    cpB(0, 0);
    CP_COMMIT();
    loadA(1);

    for (int c = 0; c < 8; c++) {
        const int cb = c & 1;
        CP_WAIT0();
        __syncthreads();
        if (c < 7) {
            storeA(dynsmem + (cb ^ 1) * BUFB);   // chunk c+1
            cpB((uint32_t)(cb ^ 1) * BUFB, c + 1);
            CP_COMMIT();
            if (c < 6) loadA(c + 2);
        }
        // ---- compute on buf cb: four k16 steps, 2 products each ----
        const uint32_t bb = (uint32_t)cb * BUFB;
#pragma unroll
        for (int ks = 0; ks < 4; ks++) {
            const uint32_t ko = (uint32_t)ks * 32;   // 16 halves = 32 bytes
            uint32_t a1[4][4], a2[4][4];
#pragma unroll
            for (int i = 0; i < 4; i++) {
                ldsm_x4(a1[i], aAddr[i] + bb + ko);
                ldsm_x4(a2[i], aAddr[i] + bb + ko + MATB);
            }
            uint32_t b[8];
            ldsm_x4(b + 0, bAddr[0] + bb + ko);
            ldsm_x4(b + 4, bAddr[1] + bb + ko);
#pragma unroll
            for (int i = 0; i < 4; i++)
#pragma unroll
                for (int j = 0; j < 4; j++) {
                    mma_f16(acc[i][j], a1[i], b[2 * j], b[2 * j + 1]);
                    mma_f16(acc[i][j], a2[i], b[2 * j], b[2 * j + 1]);
                }
        }
    }

    // ---- epilogue: acc already in true scale ----
    const int r0 = lane >> 2;
    const int c0 = (lane & 3) * 2;
#pragma unroll
    for (int i = 0; i < 4; i++) {
        const int mrow = m0 + wm * 64 + i * 16 + r0;
#pragma unroll
        for (int j = 0; j < 4; j++) {
            const int col = wn * 32 + j * 8 + c0;
            *(float2*)&z[(size_t)mrow * NOUT + col] =
                make_float2(acc[i][j][0], acc[i][j][1]);
            *(float2*)&z[(size_t)(mrow + 8) * NOUT + col] =
                make_float2(acc[i][j][2], acc[i][j][3]);
        }
    }
}

// ---------------------------------------------------------------------------
// Scan stage A: zero-state segment responses, 4 chains/thread, 16-deep buffer.
// ---------------------------------------------------------------------------
__global__ __launch_bounds__(256)
void scan_segA(const float* __restrict__ zv,
               const float* __restrict__ tau_syn, const float* __restrict__ tau_mem) {
    const int t = blockIdx.x * 256 + threadIdx.x;
    const int ch4 = (t & 2047) * 4;
    const int p = t >> 11;
    const float tm = fminf(fmaxf(tau_mem[0], 0.f), 1.f);
    const float ts = fminf(fmaxf(tau_syn[0], 0.f), 1.f);
    const float A = DTC * tm, B = DTC * ts;

    const float* zp = zv + (size_t)(p * SEG_L) * NCH + ch4;
    float v[4] = {0, 0, 0, 0}, cu[4] = {0, 0, 0, 0};
    float4 buf[16];
#pragma unroll
    for (int g = 0; g < SEG_L; g += 16) {
#pragma unroll
        for (int j = 0; j < 16; j++) buf[j] = *(const float4*)(zp + (g + j) * NCH);
#pragma unroll
        for (int j = 0; j < 16; j++) {
            const float* zb = (const float*)&buf[j];
#pragma unroll
            for (int q = 0; q < 4; q++) {
                v[q]  = fmaf(A, cu[q] - v[q], v[q]);
                cu[q] = fmaf(-B, cu[q], cu[q]) + zb[q];
            }
        }
    }
    *(float4*)&g_segE_v[p * NCH + ch4] = make_float4(v[0], v[1], v[2], v[3]);
    *(float4*)&g_segE_i[p * NCH + ch4] = make_float4(cu[0], cu[1], cu[2], cu[3]);
}

// ---------------------------------------------------------------------------
// Scan stage B: per chain, scan SEG_P summaries (all loads prefetched).
// ---------------------------------------------------------------------------
__global__ __launch_bounds__(256)
void scan_segB(const float* __restrict__ tau_syn, const float* __restrict__ tau_mem) {
    const int chain = blockIdx.x * 256 + threadIdx.x;
    const float tm = fminf(fmaxf(tau_mem[0], 0.f), 1.f);
    const float ts = fminf(fmaxf(tau_syn[0], 0.f), 1.f);
    const float A = DTC * tm, B = DTC * ts;
    const float a = 1.f - A, b = 1.f - B;

    float ev[SEG_P], ei[SEG_P];
#pragma unroll
    for (int p = 0; p < SEG_P; p++) {
        ev[p] = g_segE_v[p * NCH + chain];
        ei[p] = g_segE_i[p * NCH + chain];
    }

    float pa = 1.f, pc = 0.f, pb = 1.f;   // M^SEG_L = [[pa,pc],[0,pb]]
#pragma unroll
    for (int k = 0; k < SEG_L; k++) {
        pc = a * pc + A * pb;
        pa = a * pa;
        pb = b * pb;
    }

    float v = 0.f, cur = 0.f;
#pragma unroll
    for (int p = 0; p < SEG_P; p++) {
        g_init_v[p * NCH + chain] = v;
        g_init_i[p * NCH + chain] = cur;
        const float nv = pa * v + pc * cur + ev[p];
        const float ni = pb * cur + ei[p];
        v = nv; cur = ni;
    }
}

// ---------------------------------------------------------------------------
// Scan stage C: exact per-segment recompute + in-place voltage write, x4.
// ---------------------------------------------------------------------------
__global__ __launch_bounds__(256)
void scan_segC(float* __restrict__ zv, float* __restrict__ vf, float* __restrict__ iff,
               const float* __restrict__ tau_syn, const float* __restrict__ tau_mem,
               int write_finals) {
    const int t = blockIdx.x * 256 + threadIdx.x;
    const int ch4 = (t & 2047) * 4;
    const int p = t >> 11;
    const float tm = fminf(fmaxf(tau_mem[0], 0.f), 1.f);
    const float ts = fminf(fmaxf(tau_syn[0], 0.f), 1.f);
    const float A = DTC * tm, B = DTC * ts;

    float4 v4 = *(const float4*)&g_init_v[p * NCH + ch4];
    float4 i4 = *(const float4*)&g_init_i[p * NCH + ch4];
    float v[4] = {v4.x, v4.y, v4.z, v4.w};
    float cu[4] = {i4.x, i4.y, i4.z, i4.w};

    float* zp = zv + (size_t)(p * SEG_L) * NCH + ch4;
    float4 buf[16];
#pragma unroll
    for (int g = 0; g < SEG_L; g += 16) {
#pragma unroll
        for (int j = 0; j < 16; j++) buf[j] = *(const float4*)(zp + (g + j) * NCH);
#pragma unroll
        for (int j = 0; j < 16; j++) {
            const float* zb = (const float*)&buf[j];
            float4 vo;
#pragma unroll
            for (int q = 0; q < 4; q++) {
                v[q] = fmaf(A, cu[q] - v[q], v[q]);
                ((float*)&vo)[q] = v[q];
                cu[q] = fmaf(-B, cu[q], cu[q]) + zb[q];
            }
            *(float4*)(zp + (g + j) * NCH) = vo;
        }
    }
    if (write_finals && p == SEG_P - 1) {
        *(float4*)&vf[ch4]  = make_float4(v[0], v[1], v[2], v[3]);
        *(float4*)&iff[ch4] = make_float4(cu[0], cu[1], cu[2], cu[3]);
    }
}

// ---------------------------------------------------------------------------
extern "C" void kernel_launch(void* const* d_in, const int* in_sizes, int n_in,
                              void* d_out, int out_size) {
    const float* x = nullptr;
    const float* W = nullptr;
    const float* t_syn = nullptr;
    const float* t_mem = nullptr;
    for (int i = 0; i < n_in; i++) {
        if (in_sizes[i] == MROWS * HID)     x = (const float*)d_in[i];
        else if (in_sizes[i] == NOUT * HID) W = (const float*)d_in[i];
        else if (in_sizes[i] == 1) {
            if (!t_syn) t_syn = (const float*)d_in[i];
            else        t_mem = (const float*)d_in[i];
        }
    }

    float* out = (float*)d_out;
    const int vol = SEQL * NCH;
    const int write_finals = (out_size >= vol + 2 * NCH) ? 1 : 0;

    static int smem_set = 0;
    if (!smem_set) {
        cudaFuncSetAttribute(snn_gemm_f16,
                             cudaFuncAttributeMaxDynamicSharedMemorySize, SMEMB);
        smem_set = 1;
    }

    w_preconv<<<(NOUT * HID) / 256, 256>>>(W);
    snn_gemm_f16<<<MROWS / 128, 256, SMEMB>>>(x, out);
    scan_segA<<<(SEG_P * NCH / 4) / 256, 256>>>(out, t_syn, t_mem);
    scan_segB<<<NCH / 256, 256>>>(t_syn, t_mem);
    scan_segC<<<(SEG_P * NCH / 4) / 256, 256>>>(out, out + vol, out + vol + NCH,
                                                t_syn, t_mem, write_finals);
}

// round 11
// speedup vs baseline: 1.9856x; 1.2192x over previous
#include <cuda_runtime.h>
#include <cuda_fp16.h>
#include <cstdint>

#define DTC   0.001f
#define HID   512
#define NOUT  128
#define SEQL  2048
#define NB    64
#define MROWS (SEQL * NB)     // 131072 output rows, m = s*64 + b
#define NCH   (NB * NOUT)     // 8192 recurrence chains
#define SEG_P 32
#define SEG_L 64

// ---------------- scratch (no allocation allowed) ----------------
__device__ __align__(16) float g_segE_v[SEG_P * NCH];
__device__ __align__(16) float g_segE_i[SEG_P * NCH];
__device__ __align__(16) float g_init_v[SEG_P * NCH];
__device__ __align__(16) float g_init_i[SEG_P * NCH];
__device__ __align__(16) __half g_Wh[NOUT * HID];

// ---------------- helpers ----------------
__device__ __forceinline__ uint32_t smem_u32(const void* p) {
    uint32_t a;
    asm("{ .reg .u64 t; cvta.to.shared.u64 t, %1; cvt.u32.u64 %0, t; }" : "=r"(a) : "l"(p));
    return a;
}
__device__ __forceinline__ void ldsm_x4(uint32_t* r, uint32_t addr) {
    asm volatile("ldmatrix.sync.aligned.m8n8.x4.shared.b16 {%0,%1,%2,%3}, [%4];"
                 : "=r"(r[0]), "=r"(r[1]), "=r"(r[2]), "=r"(r[3]) : "r"(addr));
}
__device__ __forceinline__ void mma_f16(float* c, const uint32_t* a,
                                        uint32_t b0, uint32_t b1) {
    asm volatile(
        "mma.sync.aligned.m16n8k16.row.col.f32.f16.f16.f32 "
        "{%0,%1,%2,%3}, {%4,%5,%6,%7}, {%8,%9}, {%0,%1,%2,%3};"
        : "+f"(c[0]), "+f"(c[1]), "+f"(c[2]), "+f"(c[3])
        : "r"(a[0]), "r"(a[1]), "r"(a[2]), "r"(a[3]), "r"(b0), "r"(b1));
}
__device__ __forceinline__ void cp16(uint32_t smaddr, const void* g) {
    asm volatile("cp.async.cg.shared.global [%0], [%1], 16;"
                 :: "r"(smaddr), "l"(g) : "memory");
}
#define CP_COMMIT() asm volatile("cp.async.commit_group;" ::: "memory")
#define CP_WAIT0()  asm volatile("cp.async.wait_group 0;" ::: "memory")

__device__ __forceinline__ uint32_t h2u(__half2 v) {
    return *reinterpret_cast<uint32_t*>(&v);
}
// split float4 into fp16-hi and fp16-residual packed half2 pairs
__device__ __forceinline__ void split4h(float4 f, uint2& hi, uint2& lo) {
    __half2 a = __floats2half2_rn(f.x, f.y);
    __half2 b = __floats2half2_rn(f.z, f.w);
    float rx = f.x - __half2float(__low2half(a));
    float ry = f.y - __half2float(__high2half(a));
    float rz = f.z - __half2float(__low2half(b));
    float rw = f.w - __half2float(__high2half(b));
    hi.x = h2u(a); hi.y = h2u(b);
    lo.x = h2u(__floats2half2_rn(rx, ry));
    lo.y = h2u(__floats2half2_rn(rz, rw));
}

// ---------------------------------------------------------------------------
__global__ __launch_bounds__(256)
void w_preconv(const float* __restrict__ W) {
    const int i = blockIdx.x * 256 + threadIdx.x;
    g_Wh[i] = __float2half_rn(W[i]);
}

// ---------------------------------------------------------------------------
// GEMM: z = x*W via 2-product fp16 mma (x = h1+h2 exact split, W = fp16).
// CTA 128x128, BK=32 (16 chunks), double-buffered, 256 threads / 8 warps,
// warp tile 64x32, *** 2 CTAs per SM *** (16 warps/SM for latency hiding).
// SMEM rows: 32 fp16 = 64B padded to 80B (ldsm conflict-free, R3-proven).
// ---------------------------------------------------------------------------
#define ROWB   80
#define MATB   (128 * ROWB)          // 10240 bytes per matrix
#define BUFB   (3 * MATB)            // Ah1, Ah2, B = 30720
#define SMEMB  (2 * BUFB)            // 61440 bytes -> 2 CTAs/SM fits

extern __shared__ char dynsmem[];

__global__ __launch_bounds__(256, 2)
void snn_gemm_f16(const float* __restrict__ x, float* __restrict__ z) {
    const int tid  = threadIdx.x;
    const int wid  = tid >> 5;
    const int lane = tid & 31;
    const int m0   = blockIdx.x * 128;
    const int wm   = wid & 1;        // 2 M groups of 64
    const int wn   = wid >> 1;       // 4 N groups of 32

    const uint32_t sm = smem_u32(dynsmem);

    // ---- A mapping: row = tid>>1, 16-float half = (tid&1)*16 ----
    const int rA = tid >> 1;
    const int hA = (tid & 1) * 16;
    const int mA = m0 + rA;
    const float* pA = x + ((size_t)(mA & 63) * SEQL + (size_t)(mA >> 6)) * HID + hA;
    const uint32_t st0 = (uint32_t)rA * ROWB + (uint32_t)hA * 2;

    // ---- B cp.async mapping: row = tid>>1, 32B half = (tid&1)*32 ----
    const __half* pB = g_Wh + (size_t)rA * HID + hA;   // hA*2 bytes = 32B half
    const uint32_t bDst = (uint32_t)(2 * MATB) + st0;

    // ---- ldsm source addresses ----
    uint32_t aAddr[4];
#pragma unroll
    for (int i = 0; i < 4; i++) {
        const int arow = wm * 64 + i * 16 + (lane & 15);
        aAddr[i] = sm + (uint32_t)arow * ROWB + ((lane >> 4) & 1) * 16;
    }
    uint32_t bAddr[2];
#pragma unroll
    for (int g = 0; g < 2; g++) {
        const int bcol = wn * 32 + g * 16 + ((lane >> 4) & 1) * 8 + (lane & 7);
        bAddr[g] = sm + (uint32_t)(2 * MATB) + (uint32_t)bcol * ROWB +
                   ((lane >> 3) & 1) * 16;
    }

    float acc[4][4][4];
#pragma unroll
    for (int i = 0; i < 4; i++)
#pragma unroll
        for (int j = 0; j < 4; j++)
#pragma unroll
            for (int q = 0; q < 4; q++) acc[i][j][q] = 0.f;

    float4 rgA[4];
    auto loadA = [&](int c) {
#pragma unroll
        for (int q = 0; q < 4; q++) rgA[q] = *(const float4*)(pA + c * 32 + q * 4);
    };
    auto storeA = [&](char* base) {
#pragma unroll
        for (int q = 0; q < 4; q++) {
            uint2 hi, lo;
            split4h(rgA[q], hi, lo);
            const uint32_t o = st0 + (uint32_t)q * 8;
            *(uint2*)(base + o) = hi;
            *(uint2*)(base + MATB + o) = lo;
        }
    };
    auto cpB = [&](uint32_t bufb, int c) {
        cp16(sm + bufb + bDst, pB + c * 32);
        cp16(sm + bufb + bDst + 16, pB + c * 32 + 8);
    };

    // ---- prologue ----
    loadA(0);
    storeA(dynsmem);
    cpB(0, 0);
    CP_COMMIT();
    loadA(1);

    for (int c = 0; c < 16; c++) {
        const int cb = c & 1;
        CP_WAIT0();
        __syncthreads();
        if (c < 15) {
            storeA(dynsmem + (cb ^ 1) * BUFB);
            cpB((uint32_t)(cb ^ 1) * BUFB, c + 1);
            CP_COMMIT();
            if (c < 14) loadA(c + 2);
        }
        // ---- compute on buf cb: two k16 steps, 2 products each ----
        const uint32_t bb = (uint32_t)cb * BUFB;
#pragma unroll
        for (int ks = 0; ks < 2; ks++) {
            const uint32_t ko = (uint32_t)ks * 32;
            uint32_t a1[4][4], a2[4][4];
#pragma unroll
            for (int i = 0; i < 4; i++) {
                ldsm_x4(a1[i], aAddr[i] + bb + ko);
                ldsm_x4(a2[i], aAddr[i] + bb + ko + MATB);
            }
            uint32_t b[8];
            ldsm_x4(b + 0, bAddr[0] + bb + ko);
            ldsm_x4(b + 4, bAddr[1] + bb + ko);
#pragma unroll
            for (int i = 0; i < 4; i++)
#pragma unroll
                for (int j = 0; j < 4; j++) {
                    mma_f16(acc[i][j], a1[i], b[2 * j], b[2 * j + 1]);
                    mma_f16(acc[i][j], a2[i], b[2 * j], b[2 * j + 1]);
                }
        }
    }

    // ---- epilogue ----
    const int r0 = lane >> 2;
    const int c0 = (lane & 3) * 2;
#pragma unroll
    for (int i = 0; i < 4; i++) {
        const int mrow = m0 + wm * 64 + i * 16 + r0;
#pragma unroll
        for (int j = 0; j < 4; j++) {
            const int col = wn * 32 + j * 8 + c0;
            *(float2*)&z[(size_t)mrow * NOUT + col] =
                make_float2(acc[i][j][0], acc[i][j][1]);
            *(float2*)&z[(size_t)(mrow + 8) * NOUT + col] =
                make_float2(acc[i][j][2], acc[i][j][3]);
        }
    }
}

// ---------------------------------------------------------------------------
// Scan stage A: zero-state segment responses, 4 chains/thread, 16-deep buffer.
// ---------------------------------------------------------------------------
__global__ __launch_bounds__(256)
void scan_segA(const float* __restrict__ zv,
               const float* __restrict__ tau_syn, const float* __restrict__ tau_mem) {
    const int t = blockIdx.x * 256 + threadIdx.x;
    const int ch4 = (t & 2047) * 4;
    const int p = t >> 11;
    const float tm = fminf(fmaxf(tau_mem[0], 0.f), 1.f);
    const float ts = fminf(fmaxf(tau_syn[0], 0.f), 1.f);
    const float A = DTC * tm, B = DTC * ts;

    const float* zp = zv + (size_t)(p * SEG_L) * NCH + ch4;
    float v[4] = {0, 0, 0, 0}, cu[4] = {0, 0, 0, 0};
    float4 buf[16];
#pragma unroll
    for (int g = 0; g < SEG_L; g += 16) {
#pragma unroll
        for (int j = 0; j < 16; j++) buf[j] = *(const float4*)(zp + (g + j) * NCH);
#pragma unroll
        for (int j = 0; j < 16; j++) {
            const float* zb = (const float*)&buf[j];
#pragma unroll
            for (int q = 0; q < 4; q++) {
                v[q]  = fmaf(A, cu[q] - v[q], v[q]);
                cu[q] = fmaf(-B, cu[q], cu[q]) + zb[q];
            }
        }
    }
    *(float4*)&g_segE_v[p * NCH + ch4] = make_float4(v[0], v[1], v[2], v[3]);
    *(float4*)&g_segE_i[p * NCH + ch4] = make_float4(cu[0], cu[1], cu[2], cu[3]);
}

// ---------------------------------------------------------------------------
// Scan stage B: per chain, scan SEG_P summaries (all loads prefetched).
// ---------------------------------------------------------------------------
__global__ __launch_bounds__(256)
void scan_segB(const float* __restrict__ tau_syn, const float* __restrict__ tau_mem) {
    const int chain = blockIdx.x * 256 + threadIdx.x;
    const float tm = fminf(fmaxf(tau_mem[0], 0.f), 1.f);
    const float ts = fminf(fmaxf(tau_syn[0], 0.f), 1.f);
    const float A = DTC * tm, B = DTC * ts;
    const float a = 1.f - A, b = 1.f - B;

    float ev[SEG_P], ei[SEG_P];
#pragma unroll
    for (int p = 0; p < SEG_P; p++) {
        ev[p] = g_segE_v[p * NCH + chain];
        ei[p] = g_segE_i[p * NCH + chain];
    }

    float pa = 1.f, pc = 0.f, pb = 1.f;   // M^SEG_L = [[pa,pc],[0,pb]]
#pragma unroll
    for (int k = 0; k < SEG_L; k++) {
        pc = a * pc + A * pb;
        pa = a * pa;
        pb = b * pb;
    }

    float v = 0.f, cur = 0.f;
#pragma unroll
    for (int p = 0; p < SEG_P; p++) {
        g_init_v[p * NCH + chain] = v;
        g_init_i[p * NCH + chain] = cur;
        const float nv = pa * v + pc * cur + ev[p];
        const float ni = pb * cur + ei[p];
        v = nv; cur = ni;
    }
}

// ---------------------------------------------------------------------------
// Scan stage C: exact per-segment recompute + in-place voltage write, x4.
// ---------------------------------------------------------------------------
__global__ __launch_bounds__(256)
void scan_segC(float* __restrict__ zv, float* __restrict__ vf, float* __restrict__ iff,
               const float* __restrict__ tau_syn, const float* __restrict__ tau_mem,
               int write_finals) {
    const int t = blockIdx.x * 256 + threadIdx.x;
    const int ch4 = (t & 2047) * 4;
    const int p = t >> 11;
    const float tm = fminf(fmaxf(tau_mem[0], 0.f), 1.f);
    const float ts = fminf(fmaxf(tau_syn[0], 0.f), 1.f);
    const float A = DTC * tm, B = DTC * ts;

    float4 v4 = *(const float4*)&g_init_v[p * NCH + ch4];
    float4 i4 = *(const float4*)&g_init_i[p * NCH + ch4];
    float v[4] = {v4.x, v4.y, v4.z, v4.w};
    float cu[4] = {i4.x, i4.y, i4.z, i4.w};

    float* zp = zv + (size_t)(p * SEG_L) * NCH + ch4;
    float4 buf[16];
#pragma unroll
    for (int g = 0; g < SEG_L; g += 16) {
#pragma unroll
        for (int j = 0; j < 16; j++) buf[j] = *(const float4*)(zp + (g + j) * NCH);
#pragma unroll
        for (int j = 0; j < 16; j++) {
            const float* zb = (const float*)&buf[j];
            float4 vo;
#pragma unroll
            for (int q = 0; q < 4; q++) {
                v[q] = fmaf(A, cu[q] - v[q], v[q]);
                ((float*)&vo)[q] = v[q];
                cu[q] = fmaf(-B, cu[q], cu[q]) + zb[q];
            }
            *(float4*)(zp + (g + j) * NCH) = vo;
        }
    }
    if (write_finals && p == SEG_P - 1) {
        *(float4*)&vf[ch4]  = make_float4(v[0], v[1], v[2], v[3]);
        *(float4*)&iff[ch4] = make_float4(cu[0], cu[1], cu[2], cu[3]);
    }
}

// ---------------------------------------------------------------------------
extern "C" void kernel_launch(void* const* d_in, const int* in_sizes, int n_in,
                              void* d_out, int out_size) {
    const float* x = nullptr;
    const float* W = nullptr;
    const float* t_syn = nullptr;
    const float* t_mem = nullptr;
    for (int i = 0; i < n_in; i++) {
        if (in_sizes[i] == MROWS * HID)     x = (const float*)d_in[i];
        else if (in_sizes[i] == NOUT * HID) W = (const float*)d_in[i];
        else if (in_sizes[i] == 1) {
            if (!t_syn) t_syn = (const float*)d_in[i];
            else        t_mem = (const float*)d_in[i];
        }
    }

    float* out = (float*)d_out;
    const int vol = SEQL * NCH;
    const int write_finals = (out_size >= vol + 2 * NCH) ? 1 : 0;

    static int smem_set = 0;
    if (!smem_set) {
        cudaFuncSetAttribute(snn_gemm_f16,
                             cudaFuncAttributeMaxDynamicSharedMemorySize, SMEMB);
        smem_set = 1;
    }

    w_preconv<<<(NOUT * HID) / 256, 256>>>(W);
    snn_gemm_f16<<<MROWS / 128, 256, SMEMB>>>(x, out);
    scan_segA<<<(SEG_P * NCH / 4) / 256, 256>>>(out, t_syn, t_mem);
    scan_segB<<<NCH / 256, 256>>>(t_syn, t_mem);
    scan_segC<<<(SEG_P * NCH / 4) / 256, 256>>>(out, out + vol, out + vol + NCH,
                                                t_syn, t_mem, write_finals);
}

// round 12
// speedup vs baseline: 2.2534x; 1.1349x over previous
#include <cuda_runtime.h>
#include <cuda_fp16.h>
#include <cstdint>

#define DTC   0.001f
#define HID   512
#define NOUT  128
#define SEQL  2048
#define NB    64
#define MROWS (SEQL * NB)     // 131072 output rows, m = s*64 + b
#define NCH   (NB * NOUT)     // 8192 recurrence chains
#define SEG_P 32
#define SEG_L 64

// ---------------- scratch (no allocation allowed) ----------------
__device__ __align__(16) float g_segE_v[SEG_P * NCH];
__device__ __align__(16) float g_segE_i[SEG_P * NCH];
__device__ __align__(16) float g_init_v[SEG_P * NCH];
__device__ __align__(16) float g_init_i[SEG_P * NCH];
__device__ __align__(16) __half g_Wh[NOUT * HID];

// ---------------- helpers ----------------
__device__ __forceinline__ uint32_t smem_u32(const void* p) {
    uint32_t a;
    asm("{ .reg .u64 t; cvta.to.shared.u64 t, %1; cvt.u32.u64 %0, t; }" : "=r"(a) : "l"(p));
    return a;
}
__device__ __forceinline__ void ldsm_x4(uint32_t* r, uint32_t addr) {
    asm volatile("ldmatrix.sync.aligned.m8n8.x4.shared.b16 {%0,%1,%2,%3}, [%4];"
                 : "=r"(r[0]), "=r"(r[1]), "=r"(r[2]), "=r"(r[3]) : "r"(addr));
}
__device__ __forceinline__ void mma_f16(float* c, const uint32_t* a,
                                        uint32_t b0, uint32_t b1) {
    asm volatile(
        "mma.sync.aligned.m16n8k16.row.col.f32.f16.f16.f32 "
        "{%0,%1,%2,%3}, {%4,%5,%6,%7}, {%8,%9}, {%0,%1,%2,%3};"
        : "+f"(c[0]), "+f"(c[1]), "+f"(c[2]), "+f"(c[3])
        : "r"(a[0]), "r"(a[1]), "r"(a[2]), "r"(a[3]), "r"(b0), "r"(b1));
}
__device__ __forceinline__ void cp16(uint32_t smaddr, const void* g) {
    asm volatile("cp.async.cg.shared.global [%0], [%1], 16;"
                 :: "r"(smaddr), "l"(g) : "memory");
}
#define CP_COMMIT() asm volatile("cp.async.commit_group;" ::: "memory")
#define CP_WAIT0()  asm volatile("cp.async.wait_group 0;" ::: "memory")

__device__ __forceinline__ uint32_t h2u(__half2 v) {
    return *reinterpret_cast<uint32_t*>(&v);
}
// convert float4 -> packed fp16x4 (RN)
__device__ __forceinline__ uint2 cvt4h(float4 f) {
    uint2 r;
    r.x = h2u(__floats2half2_rn(f.x, f.y));
    r.y = h2u(__floats2half2_rn(f.z, f.w));
    return r;
}

// ---------------------------------------------------------------------------
__global__ __launch_bounds__(256)
void w_preconv(const float* __restrict__ W) {
    const int i = blockIdx.x * 256 + threadIdx.x;
    g_Wh[i] = __float2half_rn(W[i]);
}

// ---------------------------------------------------------------------------
// GEMM: z = fp16(x) * fp16(W), single product, fp32 accumulate.
// CTA 128x128, BK=32 (16 chunks), double-buffered, 256 threads / 8 warps,
// warp tile 64x32, 2 CTAs per SM. SMEM rows 64B padded to 80B.
// ---------------------------------------------------------------------------
#define ROWB   80
#define MATB   (128 * ROWB)          // 10240 bytes per matrix
#define BUFB   (2 * MATB)            // Ah, B = 20480
#define SMEMB  (2 * BUFB)            // 40960 bytes -> 2 CTAs/SM easily

extern __shared__ char dynsmem[];

__global__ __launch_bounds__(256, 2)
void snn_gemm_f16(const float* __restrict__ x, float* __restrict__ z) {
    const int tid  = threadIdx.x;
    const int wid  = tid >> 5;
    const int lane = tid & 31;
    const int m0   = blockIdx.x * 128;
    const int wm   = wid & 1;        // 2 M groups of 64
    const int wn   = wid >> 1;       // 4 N groups of 32

    const uint32_t sm = smem_u32(dynsmem);

    // ---- A mapping: row = tid>>1, 16-float half = (tid&1)*16 ----
    const int rA = tid >> 1;
    const int hA = (tid & 1) * 16;
    const int mA = m0 + rA;
    const float* pA = x + ((size_t)(mA & 63) * SEQL + (size_t)(mA >> 6)) * HID + hA;
    const uint32_t st0 = (uint32_t)rA * ROWB + (uint32_t)hA * 2;

    // ---- B cp.async mapping ----
    const __half* pB = g_Wh + (size_t)rA * HID + hA;
    const uint32_t bDst = (uint32_t)MATB + st0;

    // ---- ldsm source addresses ----
    uint32_t aAddr[4];
#pragma unroll
    for (int i = 0; i < 4; i++) {
        const int arow = wm * 64 + i * 16 + (lane & 15);
        aAddr[i] = sm + (uint32_t)arow * ROWB + ((lane >> 4) & 1) * 16;
    }
    uint32_t bAddr[2];
#pragma unroll
    for (int g = 0; g < 2; g++) {
        const int bcol = wn * 32 + g * 16 + ((lane >> 4) & 1) * 8 + (lane & 7);
        bAddr[g] = sm + (uint32_t)MATB + (uint32_t)bcol * ROWB +
                   ((lane >> 3) & 1) * 16;
    }

    float acc[4][4][4];
#pragma unroll
    for (int i = 0; i < 4; i++)
#pragma unroll
        for (int j = 0; j < 4; j++)
#pragma unroll
            for (int q = 0; q < 4; q++) acc[i][j][q] = 0.f;

    float4 rgA[4];
    auto loadA = [&](int c) {
#pragma unroll
        for (int q = 0; q < 4; q++) rgA[q] = *(const float4*)(pA + c * 32 + q * 4);
    };
    auto storeA = [&](char* base) {
#pragma unroll
        for (int q = 0; q < 4; q++)
            *(uint2*)(base + st0 + (uint32_t)q * 8) = cvt4h(rgA[q]);
    };
    auto cpB = [&](uint32_t bufb, int c) {
        cp16(sm + bufb + bDst, pB + c * 32);
        cp16(sm + bufb + bDst + 16, pB + c * 32 + 8);
    };

    // ---- prologue ----
    loadA(0);
    storeA(dynsmem);
    cpB(0, 0);
    CP_COMMIT();
    loadA(1);

    for (int c = 0; c < 16; c++) {
        const int cb = c & 1;
        CP_WAIT0();
        __syncthreads();
        if (c < 15) {
            storeA(dynsmem + (cb ^ 1) * BUFB);
            cpB((uint32_t)(cb ^ 1) * BUFB, c + 1);
            CP_COMMIT();
            if (c < 14) loadA(c + 2);
        }
        // ---- compute on buf cb: two k16 steps, single product ----
        const uint32_t bb = (uint32_t)cb * BUFB;
#pragma unroll
        for (int ks = 0; ks < 2; ks++) {
            const uint32_t ko = (uint32_t)ks * 32;
            uint32_t a[4][4];
#pragma unroll
            for (int i = 0; i < 4; i++)
                ldsm_x4(a[i], aAddr[i] + bb + ko);
            uint32_t b[8];
            ldsm_x4(b + 0, bAddr[0] + bb + ko);
            ldsm_x4(b + 4, bAddr[1] + bb + ko);
#pragma unroll
            for (int i = 0; i < 4; i++)
#pragma unroll
                for (int j = 0; j < 4; j++)
                    mma_f16(acc[i][j], a[i], b[2 * j], b[2 * j + 1]);
        }
    }

    // ---- epilogue ----
    const int r0 = lane >> 2;
    const int c0 = (lane & 3) * 2;
#pragma unroll
    for (int i = 0; i < 4; i++) {
        const int mrow = m0 + wm * 64 + i * 16 + r0;
#pragma unroll
        for (int j = 0; j < 4; j++) {
            const int col = wn * 32 + j * 8 + c0;
            *(float2*)&z[(size_t)mrow * NOUT + col] =
                make_float2(acc[i][j][0], acc[i][j][1]);
            *(float2*)&z[(size_t)(mrow + 8) * NOUT + col] =
                make_float2(acc[i][j][2], acc[i][j][3]);
        }
    }
}

// ---------------------------------------------------------------------------
// Scan stage A: zero-state segment responses, 4 chains/thread, 16-deep buffer.
// ---------------------------------------------------------------------------
__global__ __launch_bounds__(256)
void scan_segA(const float* __restrict__ zv,
               const float* __restrict__ tau_syn, const float* __restrict__ tau_mem) {
    const int t = blockIdx.x * 256 + threadIdx.x;
    const int ch4 = (t & 2047) * 4;
    const int p = t >> 11;
    const float tm = fminf(fmaxf(tau_mem[0], 0.f), 1.f);
    const float ts = fminf(fmaxf(tau_syn[0], 0.f), 1.f);
    const float A = DTC * tm, B = DTC * ts;

    const float* zp = zv + (size_t)(p * SEG_L) * NCH + ch4;
    float v[4] = {0, 0, 0, 0}, cu[4] = {0, 0, 0, 0};
    float4 buf[16];
#pragma unroll
    for (int g = 0; g < SEG_L; g += 16) {
#pragma unroll
        for (int j = 0; j < 16; j++) buf[j] = *(const float4*)(zp + (g + j) * NCH);
#pragma unroll
        for (int j = 0; j < 16; j++) {
            const float* zb = (const float*)&buf[j];
#pragma unroll
            for (int q = 0; q < 4; q++) {
                v[q]  = fmaf(A, cu[q] - v[q], v[q]);
                cu[q] = fmaf(-B, cu[q], cu[q]) + zb[q];
            }
        }
    }
    *(float4*)&g_segE_v[p * NCH + ch4] = make_float4(v[0], v[1], v[2], v[3]);
    *(float4*)&g_segE_i[p * NCH + ch4] = make_float4(cu[0], cu[1], cu[2], cu[3]);
}

// ---------------------------------------------------------------------------
// Scan stage B: per chain, scan SEG_P summaries (all loads prefetched).
// ---------------------------------------------------------------------------
__global__ __launch_bounds__(256)
void scan_segB(const float* __restrict__ tau_syn, const float* __restrict__ tau_mem) {
    const int chain = blockIdx.x * 256 + threadIdx.x;
    const float tm = fminf(fmaxf(tau_mem[0], 0.f), 1.f);
    const float ts = fminf(fmaxf(tau_syn[0], 0.f), 1.f);
    const float A = DTC * tm, B = DTC * ts;
    const float a = 1.f - A, b = 1.f - B;

    float ev[SEG_P], ei[SEG_P];
#pragma unroll
    for (int p = 0; p < SEG_P; p++) {
        ev[p] = g_segE_v[p * NCH + chain];
        ei[p] = g_segE_i[p * NCH + chain];
    }

    float pa = 1.f, pc = 0.f, pb = 1.f;   // M^SEG_L = [[pa,pc],[0,pb]]
#pragma unroll
    for (int k = 0; k < SEG_L; k++) {
        pc = a * pc + A * pb;
        pa = a * pa;
        pb = b * pb;
    }

    float v = 0.f, cur = 0.f;
#pragma unroll
    for (int p = 0; p < SEG_P; p++) {
        g_init_v[p * NCH + chain] = v;
        g_init_i[p * NCH + chain] = cur;
        const float nv = pa * v + pc * cur + ev[p];
        const float ni = pb * cur + ei[p];
        v = nv; cur = ni;
    }
}

// ---------------------------------------------------------------------------
// Scan stage C: exact per-segment recompute + in-place voltage write, x4.
// ---------------------------------------------------------------------------
__global__ __launch_bounds__(256)
void scan_segC(float* __restrict__ zv, float* __restrict__ vf, float* __restrict__ iff,
               const float* __restrict__ tau_syn, const float* __restrict__ tau_mem,
               int write_finals) {
    const int t = blockIdx.x * 256 + threadIdx.x;
    const int ch4 = (t & 2047) * 4;
    const int p = t >> 11;
    const float tm = fminf(fmaxf(tau_mem[0], 0.f), 1.f);
    const float ts = fminf(fmaxf(tau_syn[0], 0.f), 1.f);
    const float A = DTC * tm, B = DTC * ts;

    float4 v4 = *(const float4*)&g_init_v[p * NCH + ch4];
    float4 i4 = *(const float4*)&g_init_i[p * NCH + ch4];
    float v[4] = {v4.x, v4.y, v4.z, v4.w};
    float cu[4] = {i4.x, i4.y, i4.z, i4.w};

    float* zp = zv + (size_t)(p * SEG_L) * NCH + ch4;
    float4 buf[16];
#pragma unroll
    for (int g = 0; g < SEG_L; g += 16) {
#pragma unroll
        for (int j = 0; j < 16; j++) buf[j] = *(const float4*)(zp + (g + j) * NCH);
#pragma unroll
        for (int j = 0; j < 16; j++) {
            const float* zb = (const float*)&buf[j];
            float4 vo;
#pragma unroll
            for (int q = 0; q < 4; q++) {
                v[q] = fmaf(A, cu[q] - v[q], v[q]);
                ((float*)&vo)[q] = v[q];
                cu[q] = fmaf(-B, cu[q], cu[q]) + zb[q];
            }
            *(float4*)(zp + (g + j) * NCH) = vo;
        }
    }
    if (write_finals && p == SEG_P - 1) {
        *(float4*)&vf[ch4]  = make_float4(v[0], v[1], v[2], v[3]);
        *(float4*)&iff[ch4] = make_float4(cu[0], cu[1], cu[2], cu[3]);
    }
}

// ---------------------------------------------------------------------------
extern "C" void kernel_launch(void* const* d_in, const int* in_sizes, int n_in,
                              void* d_out, int out_size) {
    const float* x = nullptr;
    const float* W = nullptr;
    const float* t_syn = nullptr;
    const float* t_mem = nullptr;
    for (int i = 0; i < n_in; i++) {
        if (in_sizes[i] == MROWS * HID)     x = (const float*)d_in[i];
        else if (in_sizes[i] == NOUT * HID) W = (const float*)d_in[i];
        else if (in_sizes[i] == 1) {
            if (!t_syn) t_syn = (const float*)d_in[i];
            else        t_mem = (const float*)d_in[i];
        }
    }

    float* out = (float*)d_out;
    const int vol = SEQL * NCH;
    const int write_finals = (out_size >= vol + 2 * NCH) ? 1 : 0;

    static int smem_set = 0;
    if (!smem_set) {
        cudaFuncSetAttribute(snn_gemm_f16,
                             cudaFuncAttributeMaxDynamicSharedMemorySize, SMEMB);
        smem_set = 1;
    }

    w_preconv<<<(NOUT * HID) / 256, 256>>>(W);
    snn_gemm_f16<<<MROWS / 128, 256, SMEMB>>>(x, out);
    scan_segA<<<(SEG_P * NCH / 4) / 256, 256>>>(out, t_syn, t_mem);
    scan_segB<<<NCH / 256, 256>>>(t_syn, t_mem);
    scan_segC<<<(SEG_P * NCH / 4) / 256, 256>>>(out, out + vol, out + vol + NCH,
                                                t_syn, t_mem, write_finals);
}